// round 1
// baseline (speedup 1.0000x reference)
#include <cuda_runtime.h>
#include <math.h>

#define RDIM 256
#define SDIM 1024
#define CDIM 256
#define NT   16
#define STILE 64

typedef unsigned long long ull;

// scratch (static device allocations are allowed)
__device__ float g_kv[RDIM*SDIM*64];          // per token: [0:32)=k, [32:64)=v
__device__ float g_qpool_part[RDIM*NT*CDIM];
__device__ float g_msum_part[RDIM*NT];
__device__ float g_gate[RDIM*CDIM];           // attention output o[r, h*32+c]

__device__ __forceinline__ ull pk2(float x, float y){
  ull r; asm("mov.b64 %0, {%1, %2};" : "=l"(r) : "f"(x), "f"(y)); return r;
}
__device__ __forceinline__ float2 unpk2(ull v){
  float2 f; asm("mov.b64 {%0, %1}, %2;" : "=f"(f.x), "=f"(f.y) : "l"(v)); return f;
}
__device__ __forceinline__ void ffma2(ull &a, ull b, ull c){
  asm("fma.rn.f32x2 %0, %1, %2, %0;" : "+l"(a) : "l"(b), "l"(c));
}
union F4U { float4 f; ull u[2]; };

// ---------------- Kernel A: k/v projection + qpool partials ----------------
// grid (NT, RDIM), block 256. dyn smem: Ws[256*64] + ms[32*66]
__global__ void __launch_bounds__(256) ka_kv(const float* __restrict__ m,
                                             const float* __restrict__ mask,
                                             const float* __restrict__ Wk,
                                             const float* __restrict__ Wv)
{
  extern __shared__ float sm[];
  float* Ws = sm;               // [256][64]  (k outputs 0..31, v outputs 32..63)
  float* ms = sm + 256*64;      // [32][66] transposed m chunk
  const int t = threadIdx.x;
  const int r = blockIdx.y, tile = blockIdx.x, s0 = tile*STILE;

  #pragma unroll
  for (int i=0;i<32;i++){
    int f = t + 256*i;          // 0..8191
    int c = f>>5, j = f&31;
    Ws[c*64+j]    = Wk[f];
    Ws[c*64+32+j] = Wv[f];
  }

  const float* mrow = m + (r*SDIM + s0)*CDIM;
  const int tp = t>>3, cs = t&7;       // 2 tokens (2tp,2tp+1) x 8 cols-groups
  ull acc[2][4];
  #pragma unroll
  for (int a=0;a<2;a++)
    #pragma unroll
    for (int b=0;b<4;b++) acc[a][b]=0ull;

  for (int kc=0;kc<8;kc++){
    __syncthreads();
    #pragma unroll
    for (int i=0;i<2;i++){
      int f = t*2+i; int tk=f>>3, q=f&7;
      float4 v4 = *(const float4*)(mrow + tk*CDIM + kc*32 + q*4);
      ms[(q*4+0)*66+tk]=v4.x; ms[(q*4+1)*66+tk]=v4.y;
      ms[(q*4+2)*66+tk]=v4.z; ms[(q*4+3)*66+tk]=v4.w;
    }
    __syncthreads();
    #pragma unroll
    for (int kk=0;kk<32;kk++){
      float2 av = *(const float2*)(ms + kk*66 + 2*tp);
      ull a0 = pk2(av.x,av.x), a1 = pk2(av.y,av.y);
      const float* wr = Ws + (kc*32+kk)*64 + cs*4;
      #pragma unroll
      for (int i=0;i<2;i++){
        F4U w; w.f = *(const float4*)(wr + 32*i);
        ffma2(acc[0][2*i],   a0, w.u[0]);
        ffma2(acc[0][2*i+1], a0, w.u[1]);
        ffma2(acc[1][2*i],   a1, w.u[0]);
        ffma2(acc[1][2*i+1], a1, w.u[1]);
      }
    }
  }
  #pragma unroll
  for (int a=0;a<2;a++){
    float* dst = g_kv + (r*SDIM + s0 + 2*tp + a)*64 + cs*4;
    #pragma unroll
    for (int i=0;i<2;i++){
      float2 lo = unpk2(acc[a][2*i]), hi = unpk2(acc[a][2*i+1]);
      *(float4*)(dst + 32*i) = make_float4(lo.x,lo.y,hi.x,hi.y);
    }
  }
  // masked qpool partial over this 64-token tile (thread t owns channel t)
  const float* mk = mask + r*SDIM + s0;
  float qa = 0.f;
  for (int tk=0;tk<STILE;tk++) qa += mrow[tk*CDIM + t] * mk[tk];
  g_qpool_part[(r*NT+tile)*CDIM + t] = qa;
  if (t==0){
    float sv=0.f;
    for (int tk=0;tk<STILE;tk++) sv += mk[tk];
    g_msum_part[r*NT+tile]=sv;
  }
}

// ---------------- Kernel B: q, logits, softmax, o ----------------
// grid RDIM, block 256 (8 warps = 8 heads for softmax)
__global__ void __launch_bounds__(256) kb_attn(const float* __restrict__ mask,
                                               const float* __restrict__ Wq)
{
  __shared__ float qp[256];
  __shared__ float qh[256];
  __shared__ float lg[8*1024];
  __shared__ float vs[64*36];
  __shared__ float msum_s;
  const int t = threadIdx.x, r = blockIdx.x;

  float qa = 0.f;
  #pragma unroll
  for (int i=0;i<NT;i++) qa += g_qpool_part[(r*NT+i)*CDIM + t];
  if (t==0){
    float s=0.f;
    #pragma unroll
    for (int i=0;i<NT;i++) s += g_msum_part[r*NT+i];
    msum_s = s;
  }
  __syncthreads();
  qp[t] = qa / (msum_s + 1e-10f);
  __syncthreads();

  float qv = 0.f;
  for (int c=0;c<CDIM;c++) qv += qp[c]*Wq[c*256+t];
  qh[t] = qv * 0.17677669529663687f;   // 32^-0.5
  __syncthreads();

  // logits
  for (int it=0; it<4; it++){
    int s = it*256 + t;
    float kreg[32];
    const float* kv = g_kv + (r*SDIM+s)*64;
    #pragma unroll
    for (int q=0;q<8;q++){
      float4 v4 = *(const float4*)(kv+4*q);
      kreg[4*q]=v4.x; kreg[4*q+1]=v4.y; kreg[4*q+2]=v4.z; kreg[4*q+3]=v4.w;
    }
    float bias = 1.0e9f*(mask[r*SDIM+s]-1.0f);
    #pragma unroll
    for (int h=0;h<8;h++){
      float d=0.f;
      #pragma unroll
      for (int q=0;q<32;q++) d += qh[h*32+q]*kreg[q];
      lg[h*1024+s] = d + bias;
    }
  }
  __syncthreads();

  // softmax: warp w handles head w
  const int w = t>>5, lane = t&31;
  {
    float mx = -3.4e38f;
    for (int s=lane; s<1024; s+=32) mx = fmaxf(mx, lg[w*1024+s]);
    #pragma unroll
    for (int o=16;o;o>>=1) mx = fmaxf(mx, __shfl_xor_sync(0xffffffffu, mx, o));
    float sum = 0.f;
    for (int s=lane; s<1024; s+=32){
      float e = __expf(lg[w*1024+s]-mx);
      lg[w*1024+s] = e; sum += e;
    }
    #pragma unroll
    for (int o=16;o;o>>=1) sum += __shfl_xor_sync(0xffffffffu, sum, o);
    float inv = 1.0f/sum;
    for (int s=lane; s<1024; s+=32) lg[w*1024+s] *= inv;
  }
  __syncthreads();

  // o[h][j] = sum_s a[h][s] * v[s][j]
  float acc = 0.f;
  for (int tile=0;tile<NT;tile++){
    #pragma unroll
    for (int i=0;i<2;i++){
      int f=t*2+i; int tk=f>>3, q=f&7;
      float4 v4 = *(const float4*)(g_kv + (r*SDIM+tile*64+tk)*64 + 32 + 4*q);
      *(float4*)(vs + tk*36 + 4*q) = v4;
    }
    __syncthreads();
    #pragma unroll 8
    for (int tk=0;tk<64;tk++) acc += lg[w*1024 + tile*64+tk] * vs[tk*36 + lane];
    __syncthreads();
  }
  g_gate[r*CDIM + t] = acc;
}

// ---------------- Kernel C: out = (sigmoid(m@Wg+bg)*o) @ Wo + bo ----------------
// grid (NT, RDIM), block 256, 2 CTAs/SM.
__global__ void __launch_bounds__(256,2) kc_gate(const float* __restrict__ m,
    const float* __restrict__ Wg, const float* __restrict__ bgp,
    const float* __restrict__ Wo, const float* __restrict__ bop,
    float* __restrict__ out)
{
  extern __shared__ float sm[];
  float* Ws  = sm;                  // [32][256] weight chunk
  float* ms  = Ws + 8192;           // [32][66] transposed m chunk
  float* Ts  = ms + 2112;           // [256][66] transposed gated intermediate
  float* og  = Ts + 16896;          // 256
  float* bgs = og + 256;            // 256
  float* bos = bgs + 256;           // 256
  const int t = threadIdx.x;
  const int r = blockIdx.y, tile = blockIdx.x, s0 = tile*STILE;
  og[t]  = g_gate[r*CDIM + t];
  bgs[t] = bgp[t];
  bos[t] = bop[t];
  const float* mrow = m + (r*SDIM+s0)*CDIM;
  const int tp = t>>3, cs = t&7;     // 2 tokens x 32 cols per thread
  ull acc[2][16];
  #pragma unroll
  for (int a=0;a<2;a++)
    #pragma unroll
    for (int i=0;i<16;i++) acc[a][i]=0ull;

  // GEMM1: T = m @ Wg
  for (int kc=0;kc<8;kc++){
    __syncthreads();
    #pragma unroll
    for (int i=0;i<2;i++){
      int f=t*2+i; int tk=f>>3, q=f&7;
      float4 v4 = *(const float4*)(mrow + tk*CDIM + kc*32 + q*4);
      ms[(q*4+0)*66+tk]=v4.x; ms[(q*4+1)*66+tk]=v4.y;
      ms[(q*4+2)*66+tk]=v4.z; ms[(q*4+3)*66+tk]=v4.w;
    }
    #pragma unroll
    for (int i=0;i<8;i++){
      int f=i*256+t; int kk=f>>6, j4=f&63;
      *(float4*)(Ws + kk*256 + 4*j4) = *(const float4*)(Wg + (kc*32+kk)*256 + 4*j4);
    }
    __syncthreads();
    #pragma unroll
    for (int kk=0;kk<32;kk++){
      float2 av = *(const float2*)(ms + kk*66 + 2*tp);
      ull a0=pk2(av.x,av.x), a1=pk2(av.y,av.y);
      const float* wr = Ws + kk*256 + cs*4;
      #pragma unroll
      for (int i=0;i<8;i++){
        F4U w; w.f = *(const float4*)(wr + 32*i);
        ffma2(acc[0][2*i],a0,w.u[0]); ffma2(acc[0][2*i+1],a0,w.u[1]);
        ffma2(acc[1][2*i],a1,w.u[0]); ffma2(acc[1][2*i+1],a1,w.u[1]);
      }
    }
  }
  __syncthreads();
  // sigmoid + gate, store transposed into Ts[col][tok]
  #pragma unroll
  for (int i=0;i<8;i++){
    int c0 = cs*4 + 32*i;
    float2 x0=unpk2(acc[0][2*i]), x1=unpk2(acc[0][2*i+1]);
    float2 y0=unpk2(acc[1][2*i]), y1=unpk2(acc[1][2*i+1]);
    float v00 = __fdividef(og[c0+0], 1.f+__expf(-(x0.x+bgs[c0+0])));
    float v01 = __fdividef(og[c0+1], 1.f+__expf(-(x0.y+bgs[c0+1])));
    float v02 = __fdividef(og[c0+2], 1.f+__expf(-(x1.x+bgs[c0+2])));
    float v03 = __fdividef(og[c0+3], 1.f+__expf(-(x1.y+bgs[c0+3])));
    float v10 = __fdividef(og[c0+0], 1.f+__expf(-(y0.x+bgs[c0+0])));
    float v11 = __fdividef(og[c0+1], 1.f+__expf(-(y0.y+bgs[c0+1])));
    float v12 = __fdividef(og[c0+2], 1.f+__expf(-(y1.x+bgs[c0+2])));
    float v13 = __fdividef(og[c0+3], 1.f+__expf(-(y1.y+bgs[c0+3])));
    *(float2*)(Ts + (c0+0)*66 + 2*tp) = make_float2(v00, v10);
    *(float2*)(Ts + (c0+1)*66 + 2*tp) = make_float2(v01, v11);
    *(float2*)(Ts + (c0+2)*66 + 2*tp) = make_float2(v02, v12);
    *(float2*)(Ts + (c0+3)*66 + 2*tp) = make_float2(v03, v13);
  }
  #pragma unroll
  for (int a=0;a<2;a++)
    #pragma unroll
    for (int i=0;i<16;i++) acc[a][i]=0ull;
  __syncthreads();

  // GEMM2: out = T @ Wo
  for (int kc=0;kc<8;kc++){
    #pragma unroll
    for (int i=0;i<8;i++){
      int f=i*256+t; int kk=f>>6, j4=f&63;
      *(float4*)(Ws + kk*256 + 4*j4) = *(const float4*)(Wo + (kc*32+kk)*256 + 4*j4);
    }
    __syncthreads();
    #pragma unroll
    for (int kk=0;kk<32;kk++){
      float2 av = *(const float2*)(Ts + (kc*32+kk)*66 + 2*tp);
      ull a0=pk2(av.x,av.x), a1=pk2(av.y,av.y);
      const float* wr = Ws + kk*256 + cs*4;
      #pragma unroll
      for (int i=0;i<8;i++){
        F4U w; w.f = *(const float4*)(wr + 32*i);
        ffma2(acc[0][2*i],a0,w.u[0]); ffma2(acc[0][2*i+1],a0,w.u[1]);
        ffma2(acc[1][2*i],a1,w.u[0]); ffma2(acc[1][2*i+1],a1,w.u[1]);
      }
    }
    __syncthreads();
  }
  // epilogue (64B-contiguous stores per 4-lane group)
  #pragma unroll
  for (int a=0;a<2;a++){
    float* orow = out + (r*SDIM + s0 + 2*tp + a)*CDIM;
    #pragma unroll
    for (int i=0;i<8;i++){
      int c0 = cs*4 + 32*i;
      float2 lo = unpk2(acc[a][2*i]), hi = unpk2(acc[a][2*i+1]);
      *(float4*)(orow + c0) = make_float4(lo.x+bos[c0+0], lo.y+bos[c0+1],
                                          hi.x+bos[c0+2], hi.y+bos[c0+3]);
    }
  }
}

extern "C" void kernel_launch(void* const* d_in, const int* in_sizes, int n_in,
                              void* d_out, int out_size)
{
  const float* m    = (const float*)d_in[0];
  const float* mask = (const float*)d_in[1];
  const float* Wq   = (const float*)d_in[2];
  const float* Wk   = (const float*)d_in[3];
  const float* Wv   = (const float*)d_in[4];
  const float* Wg   = (const float*)d_in[5];
  const float* bg   = (const float*)d_in[6];
  const float* Wo   = (const float*)d_in[7];
  const float* bo   = (const float*)d_in[8];
  float* out = (float*)d_out;

  const int A_SMEM = (256*64 + 32*66) * 4;                       // 73984 B
  const int C_SMEM = (8192 + 2112 + 16896 + 256 + 256 + 256)*4;  // 111872 B
  cudaFuncSetAttribute(ka_kv,   cudaFuncAttributeMaxDynamicSharedMemorySize, A_SMEM);
  cudaFuncSetAttribute(kc_gate, cudaFuncAttributeMaxDynamicSharedMemorySize, C_SMEM);

  ka_kv  <<<dim3(NT, RDIM), 256, A_SMEM>>>(m, mask, Wk, Wv);
  kb_attn<<<RDIM, 256>>>(mask, Wq);
  kc_gate<<<dim3(NT, RDIM), 256, C_SMEM>>>(m, Wg, bg, Wo, bo, out);
}

// round 3
// speedup vs baseline: 2.7783x; 2.7783x over previous
#include <cuda_runtime.h>
#include <math.h>
#include <stdint.h>

#define RDIM 256
#define SDIM 1024
#define CDIM 256
#define NT   16
#define STILE 64

typedef unsigned long long ull;

// ---------------- device scratch ----------------
__device__ float g_kv[RDIM*SDIM*64];          // per token: [0:32)=k, [32:64)=v
__device__ float g_qpool_part[RDIM*NT*CDIM];
__device__ float g_msum_part[RDIM*NT];
__device__ float g_gate[RDIM*CDIM];           // attention output o[r, h*32+c]
__device__ float g_WgT[CDIM*CDIM];            // Wg transposed [n][k], tf32 RNA
__device__ float g_WoT[CDIM*CDIM];            // Wo transposed [n][k], tf32 RNA

// ---------------- helpers ----------------
__device__ __forceinline__ ull pk2(float x, float y){
  ull r; asm("mov.b64 %0, {%1, %2};" : "=l"(r) : "f"(x), "f"(y)); return r;
}
__device__ __forceinline__ float2 unpk2(ull v){
  float2 f; asm("mov.b64 {%0, %1}, %2;" : "=f"(f.x), "=f"(f.y) : "l"(v)); return f;
}
__device__ __forceinline__ void ffma2(ull &a, ull b, ull c){
  asm("fma.rn.f32x2 %0, %1, %2, %0;" : "+l"(a) : "l"(b), "l"(c));
}
union F4U { float4 f; ull u[2]; };

__device__ __forceinline__ uint32_t s2u(const void* p){
  uint32_t a;
  asm("{ .reg .u64 t; cvta.to.shared.u64 t, %1; cvt.u32.u64 %0, t; }" : "=r"(a) : "l"(p));
  return a;
}
__device__ __forceinline__ uint32_t tf32r(float x){
  uint32_t u; asm("cvt.rna.tf32.f32 %0, %1;" : "=r"(u) : "f"(x)); return u;
}
__device__ __forceinline__ void cpa16(uint32_t dst, const void* src){
  asm volatile("cp.async.cg.shared.global [%0], [%1], 16;" :: "r"(dst), "l"(src));
}
#define CP_COMMIT() asm volatile("cp.async.commit_group;" ::: "memory")
#define CP_WAIT0()  asm volatile("cp.async.wait_group 0;" ::: "memory")

__device__ __forceinline__ void mma8(float d[4], const uint32_t a[4], const uint32_t b[2]){
  asm volatile(
    "mma.sync.aligned.m16n8k8.row.col.f32.tf32.tf32.f32 "
    "{%0,%1,%2,%3}, {%4,%5,%6,%7}, {%8,%9}, {%0,%1,%2,%3};"
    : "+f"(d[0]), "+f"(d[1]), "+f"(d[2]), "+f"(d[3])
    : "r"(a[0]), "r"(a[1]), "r"(a[2]), "r"(a[3]), "r"(b[0]), "r"(b[1]));
}

// ---------------- Kernel P: transpose + tf32-round weights ----------------
__global__ void __launch_bounds__(256) kprep(const float* __restrict__ Wg,
                                             const float* __restrict__ Wo)
{
  const int n = blockIdx.x, k = threadIdx.x;
  g_WgT[n*CDIM + k] = __uint_as_float(tf32r(Wg[k*CDIM + n]));
  g_WoT[n*CDIM + k] = __uint_as_float(tf32r(Wo[k*CDIM + n]));
}

// ---------------- Kernel A: k/v projection + qpool partials (FFMA2, fp32) ----------------
__global__ void __launch_bounds__(256) ka_kv(const float* __restrict__ m,
                                             const float* __restrict__ mask,
                                             const float* __restrict__ Wk,
                                             const float* __restrict__ Wv)
{
  extern __shared__ float sm[];
  float* Ws = sm;               // [256][64]
  float* ms = sm + 256*64;      // [32][66]
  const int t = threadIdx.x;
  const int r = blockIdx.y, tile = blockIdx.x, s0 = tile*STILE;

  #pragma unroll
  for (int i=0;i<32;i++){
    int f = t + 256*i;
    int c = f>>5, j = f&31;
    Ws[c*64+j]    = Wk[f];
    Ws[c*64+32+j] = Wv[f];
  }

  const float* mrow = m + (r*SDIM + s0)*CDIM;
  const int tp = t>>3, cs = t&7;
  ull acc[2][4];
  #pragma unroll
  for (int a=0;a<2;a++)
    #pragma unroll
    for (int b=0;b<4;b++) acc[a][b]=0ull;

  for (int kc=0;kc<8;kc++){
    __syncthreads();
    #pragma unroll
    for (int i=0;i<2;i++){
      int f = t*2+i; int tk=f>>3, q=f&7;
      float4 v4 = *(const float4*)(mrow + tk*CDIM + kc*32 + q*4);
      ms[(q*4+0)*66+tk]=v4.x; ms[(q*4+1)*66+tk]=v4.y;
      ms[(q*4+2)*66+tk]=v4.z; ms[(q*4+3)*66+tk]=v4.w;
    }
    __syncthreads();
    #pragma unroll
    for (int kk=0;kk<32;kk++){
      float2 av = *(const float2*)(ms + kk*66 + 2*tp);
      ull a0 = pk2(av.x,av.x), a1 = pk2(av.y,av.y);
      const float* wr = Ws + (kc*32+kk)*64 + cs*4;
      #pragma unroll
      for (int i=0;i<2;i++){
        F4U w; w.f = *(const float4*)(wr + 32*i);
        ffma2(acc[0][2*i],   a0, w.u[0]);
        ffma2(acc[0][2*i+1], a0, w.u[1]);
        ffma2(acc[1][2*i],   a1, w.u[0]);
        ffma2(acc[1][2*i+1], a1, w.u[1]);
      }
    }
  }
  #pragma unroll
  for (int a=0;a<2;a++){
    float* dst = g_kv + (r*SDIM + s0 + 2*tp + a)*64 + cs*4;
    #pragma unroll
    for (int i=0;i<2;i++){
      float2 lo = unpk2(acc[a][2*i]), hi = unpk2(acc[a][2*i+1]);
      *(float4*)(dst + 32*i) = make_float4(lo.x,lo.y,hi.x,hi.y);
    }
  }
  const float* mk = mask + r*SDIM + s0;
  float qa = 0.f;
  for (int tk=0;tk<STILE;tk++) qa += mrow[tk*CDIM + t] * mk[tk];
  g_qpool_part[(r*NT+tile)*CDIM + t] = qa;
  if (t==0){
    float sv=0.f;
    for (int tk=0;tk<STILE;tk++) sv += mk[tk];
    g_msum_part[r*NT+tile]=sv;
  }
}

// ---------------- Kernel B: q, logits, softmax, o (fp32) ----------------
__global__ void __launch_bounds__(256) kb_attn(const float* __restrict__ mask,
                                               const float* __restrict__ Wq)
{
  __shared__ float qp[256];
  __shared__ float qh[256];
  __shared__ float lg[8*1024];
  __shared__ float vs[64*36];
  __shared__ float msum_s;
  const int t = threadIdx.x, r = blockIdx.x;

  float qa = 0.f;
  #pragma unroll
  for (int i=0;i<NT;i++) qa += g_qpool_part[(r*NT+i)*CDIM + t];
  if (t==0){
    float s=0.f;
    #pragma unroll
    for (int i=0;i<NT;i++) s += g_msum_part[r*NT+i];
    msum_s = s;
  }
  __syncthreads();
  qp[t] = qa / (msum_s + 1e-10f);
  __syncthreads();

  float qv = 0.f;
  for (int c=0;c<CDIM;c++) qv += qp[c]*Wq[c*256+t];
  qh[t] = qv * 0.17677669529663687f;
  __syncthreads();

  for (int it=0; it<4; it++){
    int s = it*256 + t;
    float kreg[32];
    const float* kv = g_kv + (r*SDIM+s)*64;
    #pragma unroll
    for (int q=0;q<8;q++){
      float4 v4 = *(const float4*)(kv+4*q);
      kreg[4*q]=v4.x; kreg[4*q+1]=v4.y; kreg[4*q+2]=v4.z; kreg[4*q+3]=v4.w;
    }
    float bias = 1.0e9f*(mask[r*SDIM+s]-1.0f);
    #pragma unroll
    for (int h=0;h<8;h++){
      float d=0.f;
      #pragma unroll
      for (int q=0;q<32;q++) d += qh[h*32+q]*kreg[q];
      lg[h*1024+s] = d + bias;
    }
  }
  __syncthreads();

  const int w = t>>5, lane = t&31;
  {
    float mx = -3.4e38f;
    for (int s=lane; s<1024; s+=32) mx = fmaxf(mx, lg[w*1024+s]);
    #pragma unroll
    for (int o=16;o;o>>=1) mx = fmaxf(mx, __shfl_xor_sync(0xffffffffu, mx, o));
    float sum = 0.f;
    for (int s=lane; s<1024; s+=32){
      float e = __expf(lg[w*1024+s]-mx);
      lg[w*1024+s] = e; sum += e;
    }
    #pragma unroll
    for (int o=16;o;o>>=1) sum += __shfl_xor_sync(0xffffffffu, sum, o);
    float inv = 1.0f/sum;
    for (int s=lane; s<1024; s+=32) lg[w*1024+s] *= inv;
  }
  __syncthreads();

  float acc = 0.f;
  for (int tile=0;tile<NT;tile++){
    #pragma unroll
    for (int i=0;i<2;i++){
      int f=t*2+i; int tk=f>>3, q=f&7;
      float4 v4 = *(const float4*)(g_kv + (r*SDIM+tile*64+tk)*64 + 32 + 4*q);
      *(float4*)(vs + tk*36 + 4*q) = v4;
    }
    __syncthreads();
    #pragma unroll 8
    for (int tk=0;tk<64;tk++) acc += lg[w*1024 + tile*64+tk] * vs[tk*36 + lane];
    __syncthreads();
  }
  g_gate[r*CDIM + t] = acc;
}

// ---------------- Kernel C: out = (sigmoid(m@Wg+bg)*o) @ Wo + bo  (tf32 mma.sync) ----------------
// CTA tile 128x256, K=256 in 8 chunks of 32, cp.async double-buffered.
// 512 threads = 16 warps in 4x4 layout; warp tile 32x64.
#define KCM     128
#define AC_LD   36
#define AC_SZ   (128*36)          // floats per A chunk buffer (4608)
#define TS_LD   260
#define TS_SZ   (128*260)         // 33280 floats (A chunk bufs live inside, dead by epilogue)
#define BS_OFF  TS_SZ
#define BS_SZ   (256*36)          // 9216 floats per B buffer
#define OG_OFF  (BS_OFF + 2*BS_SZ)
#define BG_OFF  (OG_OFF + 256)
#define BO_OFF  (BG_OFF + 256)
#define KC_SMEM_BYTES ((BO_OFF + 256)*4)   // 209920

__device__ __forceinline__ void chunk_mma(const float* __restrict__ As, int ldA,
                                          const float* __restrict__ Bs,
                                          int ar0, int bn0, int lr,
                                          float acc[2][8][4])
{
  #pragma unroll
  for (int s=0;s<4;s++){
    const int k0 = s*8 + lr;
    uint32_t a[2][4], b[8][2];
    #pragma unroll
    for (int mi=0;mi<2;mi++){
      const float* ap = As + (ar0 + mi*16)*ldA + k0;
      a[mi][0]=__float_as_uint(ap[0]);
      a[mi][1]=__float_as_uint(ap[8*ldA]);
      a[mi][2]=__float_as_uint(ap[4]);
      a[mi][3]=__float_as_uint(ap[8*ldA+4]);
    }
    #pragma unroll
    for (int ni=0;ni<8;ni++){
      const float* bp = Bs + (bn0 + ni*8)*AC_LD + k0;
      b[ni][0]=__float_as_uint(bp[0]);
      b[ni][1]=__float_as_uint(bp[4]);
    }
    #pragma unroll
    for (int mi=0;mi<2;mi++)
      #pragma unroll
      for (int ni=0;ni<8;ni++)
        mma8(acc[mi][ni], a[mi], b[ni]);
  }
}

__global__ void __launch_bounds__(512,1) kc_mma(const float* __restrict__ m,
    const float* __restrict__ bgp, const float* __restrict__ bop,
    float* __restrict__ out)
{
  extern __shared__ float sm[];
  const uint32_t sbu = s2u(sm);
  const int t = threadIdx.x, lane = t&31, w = t>>5;
  const int wm = w>>2, wn = w&3;
  const int lq = lane>>2, lr = lane&3;
  const int r = blockIdx.y, tile = blockIdx.x, s0 = tile*KCM;

  if (t < 256){
    sm[OG_OFF+t] = g_gate[r*CDIM+t];
    sm[BG_OFF+t] = bgp[t];
    sm[BO_OFF+t] = bop[t];
  }

  const float4* m4   = (const float4*)(m + (size_t)(r*SDIM + s0)*CDIM);
  const float4* WgT4 = (const float4*)g_WgT;
  const float4* WoT4 = (const float4*)g_WoT;

  const int ar0 = wm*32 + lq;    // A row base (mi=0)
  const int bn0 = wn*64 + lq;    // B n base (ni=0)

  float acc[2][8][4];
  #pragma unroll
  for (int mi=0;mi<2;mi++)
    #pragma unroll
    for (int ni=0;ni<8;ni++)
      #pragma unroll
      for (int q=0;q<4;q++) acc[mi][ni][q]=0.f;

  // ---- A/B chunk async loaders ----
  // A chunk: 128 rows x 32 floats -> 1024 f4, 2/thread
  // B chunk: 256 n   x 32 floats -> 2048 f4, 4/thread
  #define LOAD_A(kc, b) do { \
    _Pragma("unroll") \
    for (int i=0;i<2;i++){ \
      int f=i*512+t; int row=f>>3, q=f&7; \
      cpa16(sbu + (uint32_t)((b)*AC_SZ + row*AC_LD + q*4)*4, m4 + row*64 + (kc)*8 + q); \
    } } while(0)
  #define LOAD_B(W4, kc, b) do { \
    _Pragma("unroll") \
    for (int i=0;i<4;i++){ \
      int f=i*512+t; int n=f>>3, q=f&7; \
      cpa16(sbu + (uint32_t)(BS_OFF + (b)*BS_SZ + n*AC_LD + q*4)*4, (W4) + n*64 + (kc)*8 + q); \
    } } while(0)

  // ================= GEMM1: G = X @ WgT =================
  LOAD_A(0,0); LOAD_B(WgT4,0,0); CP_COMMIT();
  CP_WAIT0(); __syncthreads();
  for (int kc=0;kc<8;kc++){
    if (kc<7){ LOAD_A(kc+1,(kc+1)&1); LOAD_B(WgT4,kc+1,(kc+1)&1); CP_COMMIT(); }
    chunk_mma(sm + (kc&1)*AC_SZ, AC_LD, sm + BS_OFF + (kc&1)*BS_SZ, ar0, bn0, lr, acc);
    if (kc<7) CP_WAIT0();
    __syncthreads();
  }

  // prefetch GEMM2 B chunk 0 (independent of Ts writes)
  LOAD_B(WoT4,0,0); CP_COMMIT();

  // ---- Epilogue 1: T = og * sigmoid(G + bg), tf32-RNA, into Ts ----
  #pragma unroll
  for (int mi=0;mi<2;mi++){
    #pragma unroll
    for (int ni=0;ni<8;ni++){
      const int col0 = wn*64 + ni*8 + lr*2;
      const int row0 = wm*32 + mi*16 + lq;
      const float bg0 = sm[BG_OFF+col0], bg1 = sm[BG_OFF+col0+1];
      const float o0  = sm[OG_OFF+col0], o1  = sm[OG_OFF+col0+1];
      float t00 = __fdividef(o0, 1.f+__expf(-(acc[mi][ni][0]+bg0)));
      float t01 = __fdividef(o1, 1.f+__expf(-(acc[mi][ni][1]+bg1)));
      float t10 = __fdividef(o0, 1.f+__expf(-(acc[mi][ni][2]+bg0)));
      float t11 = __fdividef(o1, 1.f+__expf(-(acc[mi][ni][3]+bg1)));
      *(float2*)(sm + row0*TS_LD + col0) =
          make_float2(__uint_as_float(tf32r(t00)), __uint_as_float(tf32r(t01)));
      *(float2*)(sm + (row0+8)*TS_LD + col0) =
          make_float2(__uint_as_float(tf32r(t10)), __uint_as_float(tf32r(t11)));
      #pragma unroll
      for (int q=0;q<4;q++) acc[mi][ni][q]=0.f;
    }
  }
  CP_WAIT0();
  __syncthreads();

  // ================= GEMM2: out = T @ WoT =================
  for (int kc=0;kc<8;kc++){
    if (kc<7){ LOAD_B(WoT4,kc+1,(kc+1)&1); CP_COMMIT(); }
    chunk_mma(sm + kc*32, TS_LD, sm + BS_OFF + (kc&1)*BS_SZ, ar0, bn0, lr, acc);
    if (kc<7) CP_WAIT0();
    __syncthreads();
  }

  // ---- Epilogue 2: add bo, store ----
  #pragma unroll
  for (int mi=0;mi<2;mi++){
    #pragma unroll
    for (int ni=0;ni<8;ni++){
      const int col0 = wn*64 + ni*8 + lr*2;
      const int row0 = wm*32 + mi*16 + lq;
      const float b0 = sm[BO_OFF+col0], b1 = sm[BO_OFF+col0+1];
      *(float2*)(out + (size_t)(r*SDIM + s0 + row0)*CDIM + col0) =
          make_float2(acc[mi][ni][0]+b0, acc[mi][ni][1]+b1);
      *(float2*)(out + (size_t)(r*SDIM + s0 + row0+8)*CDIM + col0) =
          make_float2(acc[mi][ni][2]+b0, acc[mi][ni][3]+b1);
    }
  }
  #undef LOAD_A
  #undef LOAD_B
}

// ---------------- launch ----------------
extern "C" void kernel_launch(void* const* d_in, const int* in_sizes, int n_in,
                              void* d_out, int out_size)
{
  const float* m    = (const float*)d_in[0];
  const float* mask = (const float*)d_in[1];
  const float* Wq   = (const float*)d_in[2];
  const float* Wk   = (const float*)d_in[3];
  const float* Wv   = (const float*)d_in[4];
  const float* Wg   = (const float*)d_in[5];
  const float* bg   = (const float*)d_in[6];
  const float* Wo   = (const float*)d_in[7];
  const float* bo   = (const float*)d_in[8];
  float* out = (float*)d_out;

  const int A_SMEM = (256*64 + 32*66) * 4;
  cudaFuncSetAttribute(ka_kv,  cudaFuncAttributeMaxDynamicSharedMemorySize, A_SMEM);
  cudaFuncSetAttribute(kc_mma, cudaFuncAttributeMaxDynamicSharedMemorySize, KC_SMEM_BYTES);

  kprep <<<256, 256>>>(Wg, Wo);
  ka_kv <<<dim3(NT, RDIM), 256, A_SMEM>>>(m, mask, Wk, Wv);
  kb_attn<<<RDIM, 256>>>(mask, Wq);
  kc_mma<<<dim3(8, RDIM), 512, KC_SMEM_BYTES>>>(m, bg, bo, out);
}

// round 5
// speedup vs baseline: 3.7719x; 1.3576x over previous
#include <cuda_runtime.h>
#include <math.h>
#include <stdint.h>

#define RDIM 256
#define SDIM 1024
#define CDIM 256
#define NTA  8          // 128-token tiles per row

typedef unsigned long long ull;

// ---------------- device scratch ----------------
__device__ float g_kv[RDIM*SDIM*64];          // per token: [0:32)=k, [32:64)=v
__device__ float g_qpool_part[RDIM*NTA*CDIM];
__device__ float g_msum_part[RDIM*NTA];
__device__ float g_gate[RDIM*CDIM];           // attention output o[r, h*32+c]
__device__ float g_WgT[CDIM*CDIM];            // Wg transposed [n][k], tf32 RNA
__device__ float g_WoT[CDIM*CDIM];            // Wo transposed [n][k], tf32 RNA
__device__ float g_WkvT[64*CDIM];             // [Wk|Wv] transposed [n][k], tf32 RNA

// ---------------- helpers ----------------
__device__ __forceinline__ uint32_t s2u(const void* p){
  uint32_t a;
  asm("{ .reg .u64 t; cvta.to.shared.u64 t, %1; cvt.u32.u64 %0, t; }" : "=r"(a) : "l"(p));
  return a;
}
__device__ __forceinline__ uint32_t tf32r(float x){
  uint32_t u; asm("cvt.rna.tf32.f32 %0, %1;" : "=r"(u) : "f"(x)); return u;
}
__device__ __forceinline__ void cpa16(uint32_t dst, const void* src){
  asm volatile("cp.async.cg.shared.global [%0], [%1], 16;" :: "r"(dst), "l"(src));
}
#define CP_COMMIT() asm volatile("cp.async.commit_group;" ::: "memory")
#define CP_WAIT0()  asm volatile("cp.async.wait_group 0;" ::: "memory")

__device__ __forceinline__ void mma8(float d[4], const uint32_t a[4], const uint32_t b[2]){
  asm volatile(
    "mma.sync.aligned.m16n8k8.row.col.f32.tf32.tf32.f32 "
    "{%0,%1,%2,%3}, {%4,%5,%6,%7}, {%8,%9}, {%0,%1,%2,%3};"
    : "+f"(d[0]), "+f"(d[1]), "+f"(d[2]), "+f"(d[3])
    : "r"(a[0]), "r"(a[1]), "r"(a[2]), "r"(a[3]), "r"(b[0]), "r"(b[1]));
}

// ---------------- Kernel P: transpose + tf32-round weights ----------------
__global__ void __launch_bounds__(256) kprep(const float* __restrict__ Wg,
                                             const float* __restrict__ Wo,
                                             const float* __restrict__ Wk,
                                             const float* __restrict__ Wv)
{
  const int n = blockIdx.x, k = threadIdx.x;
  g_WgT[n*CDIM + k] = __uint_as_float(tf32r(Wg[k*CDIM + n]));
  g_WoT[n*CDIM + k] = __uint_as_float(tf32r(Wo[k*CDIM + n]));
  if (n < 32)       g_WkvT[n*CDIM + k]      = __uint_as_float(tf32r(Wk[k*32 + n]));
  else if (n < 64)  g_WkvT[n*CDIM + k]      = __uint_as_float(tf32r(Wv[k*32 + (n-32)]));
}

// ---------------- Kernel A: k/v projection (tf32 mma) + fused qpool ----------------
// grid (NTA, RDIM), 256 threads (8 warps, 4x2), CTA tile 128 tok x 64 out, K=256.
#define KA_ALD   36
#define KA_ASZ   (128*KA_ALD)          // 4608 floats per A buffer
#define KA_BOFF  (2*KA_ASZ)            // 9216
#define KA_BLD   260
#define KA_MSK   (KA_BOFF + 64*KA_BLD) // 25856
#define KA_SMEM  ((KA_MSK + 128)*4)    // 103936 B

__global__ void __launch_bounds__(256,2) ka_kv(const float* __restrict__ m,
                                               const float* __restrict__ mask)
{
  extern __shared__ float sm[];
  const uint32_t sbu = s2u(sm);
  const int t = threadIdx.x, lane = t&31, w = t>>5;
  const int wm = w>>1, wn = w&1;
  const int lq = lane>>2, lr = lane&3;
  const int r = blockIdx.y, tile = blockIdx.x, s0 = tile*128;

  const float4* m4 = (const float4*)(m + (size_t)(r*SDIM + s0)*CDIM);
  const float4* B4 = (const float4*)g_WkvT;

  // stage mask
  if (t < 128) sm[KA_MSK + t] = mask[r*SDIM + s0 + t];

  // stage full B (64 x 256 = 4096 f4)
  #pragma unroll
  for (int i=0;i<16;i++){
    int f = i*256 + t; int n = f>>6, q = f&63;
    cpa16(sbu + (uint32_t)(KA_BOFF + n*KA_BLD + q*4)*4, B4 + n*64 + q);
  }
  // A chunk 0
  #pragma unroll
  for (int i=0;i<4;i++){
    int f = i*256 + t; int row = f>>3, q = f&7;
    cpa16(sbu + (uint32_t)(0*KA_ASZ + row*KA_ALD + q*4)*4, m4 + row*64 + 0*8 + q);
  }
  CP_COMMIT(); CP_WAIT0();
  __syncthreads();

  // mask sum (warp 0)
  if (t < 32){
    float s = sm[KA_MSK+t] + sm[KA_MSK+t+32] + sm[KA_MSK+t+64] + sm[KA_MSK+t+96];
    #pragma unroll
    for (int o=16;o;o>>=1) s += __shfl_xor_sync(0xffffffffu, s, o);
    if (t==0) g_msum_part[r*NTA + tile] = s;
  }

  const int ar0 = wm*32 + lq;
  const int bn0 = wn*32 + lq;
  float acc[2][4][4];
  #pragma unroll
  for (int mi=0;mi<2;mi++)
    #pragma unroll
    for (int ni=0;ni<4;ni++)
      #pragma unroll
      for (int q=0;q<4;q++) acc[mi][ni][q]=0.f;

  const int qch = t>>3, qsub = t&7;   // qpool: 8 threads per channel

  for (int kc=0;kc<8;kc++){
    if (kc<7){
      #pragma unroll
      for (int i=0;i<4;i++){
        int f = i*256 + t; int row = f>>3, q = f&7;
        cpa16(sbu + (uint32_t)(((kc+1)&1)*KA_ASZ + row*KA_ALD + q*4)*4,
              m4 + row*64 + (kc+1)*8 + q);
      }
      CP_COMMIT();
    }
    const float* As = sm + (kc&1)*KA_ASZ;
    const float* Bs = sm + KA_BOFF;
    #pragma unroll
    for (int s=0;s<4;s++){
      const int k0  = s*8 + lr;            // A chunk-relative k
      const int kb0 = kc*32 + k0;          // B absolute k (FIX: add kc*32)
      uint32_t a[2][4], b[4][2];
      #pragma unroll
      for (int mi=0;mi<2;mi++){
        const float* ap = As + (ar0 + mi*16)*KA_ALD + k0;
        a[mi][0]=__float_as_uint(ap[0]);
        a[mi][1]=__float_as_uint(ap[8*KA_ALD]);
        a[mi][2]=__float_as_uint(ap[4]);
        a[mi][3]=__float_as_uint(ap[8*KA_ALD+4]);
      }
      #pragma unroll
      for (int ni=0;ni<4;ni++){
        const float* bp = Bs + (bn0 + ni*8)*KA_BLD + kb0;
        b[ni][0]=__float_as_uint(bp[0]);
        b[ni][1]=__float_as_uint(bp[4]);
      }
      #pragma unroll
      for (int mi=0;mi<2;mi++)
        #pragma unroll
        for (int ni=0;ni<4;ni++)
          mma8(acc[mi][ni], a[mi], b[ni]);
    }
    // fused qpool partial for channels kc*32 .. kc*32+31 (exact fp32)
    {
      float qa = 0.f;
      #pragma unroll
      for (int j=0;j<16;j++){
        int row = qsub + 8*j;
        qa += As[row*KA_ALD + qch] * sm[KA_MSK + row];
      }
      qa += __shfl_xor_sync(0xffffffffu, qa, 4);
      qa += __shfl_xor_sync(0xffffffffu, qa, 2);
      qa += __shfl_xor_sync(0xffffffffu, qa, 1);
      if (qsub==0) g_qpool_part[(r*NTA + tile)*CDIM + kc*32 + qch] = qa;
    }
    if (kc<7) CP_WAIT0();
    __syncthreads();
  }

  // store k/v
  #pragma unroll
  for (int mi=0;mi<2;mi++){
    #pragma unroll
    for (int ni=0;ni<4;ni++){
      const int col0 = wn*32 + ni*8 + lr*2;
      const int row0 = wm*32 + mi*16 + lq;
      *(float2*)(g_kv + (size_t)(r*SDIM + s0 + row0)*64 + col0) =
          make_float2(acc[mi][ni][0], acc[mi][ni][1]);
      *(float2*)(g_kv + (size_t)(r*SDIM + s0 + row0+8)*64 + col0) =
          make_float2(acc[mi][ni][2], acc[mi][ni][3]);
    }
  }
}

// ---------------- Kernel B: q, logits, softmax, o (fp32) ----------------
__global__ void __launch_bounds__(256) kb_attn(const float* __restrict__ mask,
                                               const float* __restrict__ Wq)
{
  __shared__ float qp[256];
  __shared__ float qh[256];
  __shared__ float lg[8*1024];
  __shared__ float vs[64*36];
  __shared__ float msum_s;
  const int t = threadIdx.x, r = blockIdx.x;

  float qa = 0.f;
  #pragma unroll
  for (int i=0;i<NTA;i++) qa += g_qpool_part[(r*NTA+i)*CDIM + t];
  if (t==0){
    float s=0.f;
    #pragma unroll
    for (int i=0;i<NTA;i++) s += g_msum_part[r*NTA+i];
    msum_s = s;
  }
  __syncthreads();
  qp[t] = qa / (msum_s + 1e-10f);
  __syncthreads();

  float qv = 0.f;
  for (int c=0;c<CDIM;c++) qv += qp[c]*Wq[c*256+t];
  qh[t] = qv * 0.17677669529663687f;
  __syncthreads();

  for (int it=0; it<4; it++){
    int s = it*256 + t;
    float kreg[32];
    const float* kv = g_kv + (size_t)(r*SDIM+s)*64;
    #pragma unroll
    for (int q=0;q<8;q++){
      float4 v4 = *(const float4*)(kv+4*q);
      kreg[4*q]=v4.x; kreg[4*q+1]=v4.y; kreg[4*q+2]=v4.z; kreg[4*q+3]=v4.w;
    }
    float bias = 1.0e9f*(mask[r*SDIM+s]-1.0f);
    #pragma unroll
    for (int h=0;h<8;h++){
      float d=0.f;
      #pragma unroll
      for (int q=0;q<32;q++) d += qh[h*32+q]*kreg[q];
      lg[h*1024+s] = d + bias;
    }
  }
  __syncthreads();

  const int w = t>>5, lane = t&31;
  {
    float mx = -3.4e38f;
    for (int s=lane; s<1024; s+=32) mx = fmaxf(mx, lg[w*1024+s]);
    #pragma unroll
    for (int o=16;o;o>>=1) mx = fmaxf(mx, __shfl_xor_sync(0xffffffffu, mx, o));
    float sum = 0.f;
    for (int s=lane; s<1024; s+=32){
      float e = __expf(lg[w*1024+s]-mx);
      lg[w*1024+s] = e; sum += e;
    }
    #pragma unroll
    for (int o=16;o;o>>=1) sum += __shfl_xor_sync(0xffffffffu, sum, o);
    float inv = 1.0f/sum;
    for (int s=lane; s<1024; s+=32) lg[w*1024+s] *= inv;
  }
  __syncthreads();

  float acc = 0.f;
  for (int tile=0;tile<16;tile++){
    #pragma unroll
    for (int i=0;i<2;i++){
      int f=t*2+i; int tk=f>>3, q=f&7;
      float4 v4 = *(const float4*)(g_kv + (size_t)(r*SDIM+tile*64+tk)*64 + 32 + 4*q);
      *(float4*)(vs + tk*36 + 4*q) = v4;
    }
    __syncthreads();
    #pragma unroll 8
    for (int tk=0;tk<64;tk++) acc += lg[w*1024 + tile*64+tk] * vs[tk*36 + lane];
    __syncthreads();
  }
  g_gate[r*CDIM + t] = acc;
}

// ---------------- Kernel C: out = (sigmoid(m@Wg+bg)*o) @ Wo + bo  (tf32 mma.sync) ----------------
#define KCM     128
#define AC_LD   36
#define AC_SZ   (128*36)
#define TS_LD   260
#define TS_SZ   (128*260)
#define BS_OFF  TS_SZ
#define BS_SZ   (256*36)
#define OG_OFF  (BS_OFF + 2*BS_SZ)
#define BG_OFF  (OG_OFF + 256)
#define BO_OFF  (BG_OFF + 256)
#define KC_SMEM_BYTES ((BO_OFF + 256)*4)   // 209920

__device__ __forceinline__ void chunk_mma(const float* __restrict__ As, int ldA,
                                          const float* __restrict__ Bs,
                                          int ar0, int bn0, int lr,
                                          float acc[2][8][4])
{
  #pragma unroll
  for (int s=0;s<4;s++){
    const int k0 = s*8 + lr;
    uint32_t a[2][4], b[8][2];
    #pragma unroll
    for (int mi=0;mi<2;mi++){
      const float* ap = As + (ar0 + mi*16)*ldA + k0;
      a[mi][0]=__float_as_uint(ap[0]);
      a[mi][1]=__float_as_uint(ap[8*ldA]);
      a[mi][2]=__float_as_uint(ap[4]);
      a[mi][3]=__float_as_uint(ap[8*ldA+4]);
    }
    #pragma unroll
    for (int ni=0;ni<8;ni++){
      const float* bp = Bs + (bn0 + ni*8)*AC_LD + k0;
      b[ni][0]=__float_as_uint(bp[0]);
      b[ni][1]=__float_as_uint(bp[4]);
    }
    #pragma unroll
    for (int mi=0;mi<2;mi++)
      #pragma unroll
      for (int ni=0;ni<8;ni++)
        mma8(acc[mi][ni], a[mi], b[ni]);
  }
}

__global__ void __launch_bounds__(512,1) kc_mma(const float* __restrict__ m,
    const float* __restrict__ bgp, const float* __restrict__ bop,
    float* __restrict__ out)
{
  extern __shared__ float sm[];
  const uint32_t sbu = s2u(sm);
  const int t = threadIdx.x, lane = t&31, w = t>>5;
  const int wm = w>>2, wn = w&3;
  const int lq = lane>>2, lr = lane&3;
  const int r = blockIdx.y, tile = blockIdx.x, s0 = tile*KCM;

  if (t < 256){
    sm[OG_OFF+t] = g_gate[r*CDIM+t];
    sm[BG_OFF+t] = bgp[t];
    sm[BO_OFF+t] = bop[t];
  }

  const float4* m4   = (const float4*)(m + (size_t)(r*SDIM + s0)*CDIM);
  const float4* WgT4 = (const float4*)g_WgT;
  const float4* WoT4 = (const float4*)g_WoT;

  const int ar0 = wm*32 + lq;
  const int bn0 = wn*64 + lq;

  float acc[2][8][4];
  #pragma unroll
  for (int mi=0;mi<2;mi++)
    #pragma unroll
    for (int ni=0;ni<8;ni++)
      #pragma unroll
      for (int q=0;q<4;q++) acc[mi][ni][q]=0.f;

  #define LOAD_A(kc, b) do { \
    _Pragma("unroll") \
    for (int i=0;i<2;i++){ \
      int f=i*512+t; int row=f>>3, q=f&7; \
      cpa16(sbu + (uint32_t)((b)*AC_SZ + row*AC_LD + q*4)*4, m4 + row*64 + (kc)*8 + q); \
    } } while(0)
  #define LOAD_B(W4, kc, b) do { \
    _Pragma("unroll") \
    for (int i=0;i<4;i++){ \
      int f=i*512+t; int n=f>>3, q=f&7; \
      cpa16(sbu + (uint32_t)(BS_OFF + (b)*BS_SZ + n*AC_LD + q*4)*4, (W4) + n*64 + (kc)*8 + q); \
    } } while(0)

  // ================= GEMM1: G = X @ WgT =================
  LOAD_A(0,0); LOAD_B(WgT4,0,0); CP_COMMIT();
  CP_WAIT0(); __syncthreads();
  for (int kc=0;kc<8;kc++){
    if (kc<7){ LOAD_A(kc+1,(kc+1)&1); LOAD_B(WgT4,kc+1,(kc+1)&1); CP_COMMIT(); }
    chunk_mma(sm + (kc&1)*AC_SZ, AC_LD, sm + BS_OFF + (kc&1)*BS_SZ, ar0, bn0, lr, acc);
    if (kc<7) CP_WAIT0();
    __syncthreads();
  }

  LOAD_B(WoT4,0,0); CP_COMMIT();

  // ---- Epilogue 1: T = og * sigmoid(G + bg), tf32-RNA, into Ts ----
  #pragma unroll
  for (int mi=0;mi<2;mi++){
    #pragma unroll
    for (int ni=0;ni<8;ni++){
      const int col0 = wn*64 + ni*8 + lr*2;
      const int row0 = wm*32 + mi*16 + lq;
      const float bg0 = sm[BG_OFF+col0], bg1 = sm[BG_OFF+col0+1];
      const float o0  = sm[OG_OFF+col0], o1  = sm[OG_OFF+col0+1];
      float t00 = __fdividef(o0, 1.f+__expf(-(acc[mi][ni][0]+bg0)));
      float t01 = __fdividef(o1, 1.f+__expf(-(acc[mi][ni][1]+bg1)));
      float t10 = __fdividef(o0, 1.f+__expf(-(acc[mi][ni][2]+bg0)));
      float t11 = __fdividef(o1, 1.f+__expf(-(acc[mi][ni][3]+bg1)));
      *(float2*)(sm + row0*TS_LD + col0) =
          make_float2(__uint_as_float(tf32r(t00)), __uint_as_float(tf32r(t01)));
      *(float2*)(sm + (row0+8)*TS_LD + col0) =
          make_float2(__uint_as_float(tf32r(t10)), __uint_as_float(tf32r(t11)));
      #pragma unroll
      for (int q=0;q<4;q++) acc[mi][ni][q]=0.f;
    }
  }
  CP_WAIT0();
  __syncthreads();

  // ================= GEMM2: out = T @ WoT =================
  for (int kc=0;kc<8;kc++){
    if (kc<7){ LOAD_B(WoT4,kc+1,(kc+1)&1); CP_COMMIT(); }
    chunk_mma(sm + kc*32, TS_LD, sm + BS_OFF + (kc&1)*BS_SZ, ar0, bn0, lr, acc);
    if (kc<7) CP_WAIT0();
    __syncthreads();
  }

  // ---- Epilogue 2: add bo, store ----
  #pragma unroll
  for (int mi=0;mi<2;mi++){
    #pragma unroll
    for (int ni=0;ni<8;ni++){
      const int col0 = wn*64 + ni*8 + lr*2;
      const int row0 = wm*32 + mi*16 + lq;
      const float b0 = sm[BO_OFF+col0], b1 = sm[BO_OFF+col0+1];
      *(float2*)(out + (size_t)(r*SDIM + s0 + row0)*CDIM + col0) =
          make_float2(acc[mi][ni][0]+b0, acc[mi][ni][1]+b1);
      *(float2*)(out + (size_t)(r*SDIM + s0 + row0+8)*CDIM + col0) =
          make_float2(acc[mi][ni][2]+b0, acc[mi][ni][3]+b1);
    }
  }
  #undef LOAD_A
  #undef LOAD_B
}

// ---------------- launch ----------------
extern "C" void kernel_launch(void* const* d_in, const int* in_sizes, int n_in,
                              void* d_out, int out_size)
{
  const float* m    = (const float*)d_in[0];
  const float* mask = (const float*)d_in[1];
  const float* Wq   = (const float*)d_in[2];
  const float* Wk   = (const float*)d_in[3];
  const float* Wv   = (const float*)d_in[4];
  const float* Wg   = (const float*)d_in[5];
  const float* bg   = (const float*)d_in[6];
  const float* Wo   = (const float*)d_in[7];
  const float* bo   = (const float*)d_in[8];
  float* out = (float*)d_out;

  cudaFuncSetAttribute(ka_kv,  cudaFuncAttributeMaxDynamicSharedMemorySize, KA_SMEM);
  cudaFuncSetAttribute(kc_mma, cudaFuncAttributeMaxDynamicSharedMemorySize, KC_SMEM_BYTES);

  kprep <<<256, 256>>>(Wg, Wo, Wk, Wv);
  ka_kv <<<dim3(NTA, RDIM), 256, KA_SMEM>>>(m, mask);
  kb_attn<<<RDIM, 256>>>(mask, Wq);
  kc_mma<<<dim3(8, RDIM), 512, KC_SMEM_BYTES>>>(m, bg, bo, out);
}

// round 6
// speedup vs baseline: 3.8396x; 1.0179x over previous
#include <cuda_runtime.h>
#include <math.h>
#include <stdint.h>

#define RDIM 256
#define SDIM 1024
#define CDIM 256
#define NTA  8          // 128-token tiles per row

typedef unsigned long long ull;

// ---------------- device scratch ----------------
__device__ float g_kv[RDIM*SDIM*64];          // per token: [0:32)=k, [32:64)=v
__device__ float g_qpool_part[RDIM*NTA*CDIM];
__device__ float g_msum_part[RDIM*NTA];
__device__ float g_gate[RDIM*CDIM];           // attention output o[r, h*32+c]
__device__ float g_WgT[CDIM*CDIM];            // Wg transposed [n][k], tf32 RNA
__device__ float g_WoT[CDIM*CDIM];            // Wo transposed [n][k], tf32 RNA
__device__ float g_WkvT[64*CDIM];             // [Wk|Wv] transposed [n][k], tf32 RNA

// ---------------- helpers ----------------
__device__ __forceinline__ uint32_t s2u(const void* p){
  uint32_t a;
  asm("{ .reg .u64 t; cvta.to.shared.u64 t, %1; cvt.u32.u64 %0, t; }" : "=r"(a) : "l"(p));
  return a;
}
__device__ __forceinline__ uint32_t tf32r(float x){
  uint32_t u; asm("cvt.rna.tf32.f32 %0, %1;" : "=r"(u) : "f"(x)); return u;
}
__device__ __forceinline__ void cpa16(uint32_t dst, const void* src){
  asm volatile("cp.async.cg.shared.global [%0], [%1], 16;" :: "r"(dst), "l"(src));
}
#define CP_COMMIT() asm volatile("cp.async.commit_group;" ::: "memory")
#define CP_WAIT0()  asm volatile("cp.async.wait_group 0;" ::: "memory")

__device__ __forceinline__ void mma8(float d[4], const uint32_t a[4], const uint32_t b[2]){
  asm volatile(
    "mma.sync.aligned.m16n8k8.row.col.f32.tf32.tf32.f32 "
    "{%0,%1,%2,%3}, {%4,%5,%6,%7}, {%8,%9}, {%0,%1,%2,%3};"
    : "+f"(d[0]), "+f"(d[1]), "+f"(d[2]), "+f"(d[3])
    : "r"(a[0]), "r"(a[1]), "r"(a[2]), "r"(a[3]), "r"(b[0]), "r"(b[1]));
}

// ---------------- Kernel P: transpose + tf32-round weights ----------------
__global__ void __launch_bounds__(256) kprep(const float* __restrict__ Wg,
                                             const float* __restrict__ Wo,
                                             const float* __restrict__ Wk,
                                             const float* __restrict__ Wv)
{
  const int n = blockIdx.x, k = threadIdx.x;
  g_WgT[n*CDIM + k] = __uint_as_float(tf32r(Wg[k*CDIM + n]));
  g_WoT[n*CDIM + k] = __uint_as_float(tf32r(Wo[k*CDIM + n]));
  if (n < 32)       g_WkvT[n*CDIM + k]      = __uint_as_float(tf32r(Wk[k*32 + n]));
  else if (n < 64)  g_WkvT[n*CDIM + k]      = __uint_as_float(tf32r(Wv[k*32 + (n-32)]));
}

// ---------------- Kernel A: k/v projection (tf32 mma) + fused qpool ----------------
// grid (NTA, RDIM), 256 threads (8 warps, 4x2), CTA tile 128 tok x 64 out, K=256.
#define KA_ALD   36
#define KA_ASZ   (128*KA_ALD)          // 4608 floats per A buffer
#define KA_BOFF  (2*KA_ASZ)            // 9216
#define KA_BLD   260
#define KA_MSK   (KA_BOFF + 64*KA_BLD) // 25856
#define KA_SMEM  ((KA_MSK + 128)*4)    // 103936 B

__global__ void __launch_bounds__(256,2) ka_kv(const float* __restrict__ m,
                                               const float* __restrict__ mask)
{
  extern __shared__ float sm[];
  const uint32_t sbu = s2u(sm);
  const int t = threadIdx.x, lane = t&31, w = t>>5;
  const int wm = w>>1, wn = w&1;
  const int lq = lane>>2, lr = lane&3;
  const int r = blockIdx.y, tile = blockIdx.x, s0 = tile*128;

  const float4* m4 = (const float4*)(m + (size_t)(r*SDIM + s0)*CDIM);
  const float4* B4 = (const float4*)g_WkvT;

  // stage mask
  if (t < 128) sm[KA_MSK + t] = mask[r*SDIM + s0 + t];

  // stage full B (64 x 256 = 4096 f4)
  #pragma unroll
  for (int i=0;i<16;i++){
    int f = i*256 + t; int n = f>>6, q = f&63;
    cpa16(sbu + (uint32_t)(KA_BOFF + n*KA_BLD + q*4)*4, B4 + n*64 + q);
  }
  // A chunk 0
  #pragma unroll
  for (int i=0;i<4;i++){
    int f = i*256 + t; int row = f>>3, q = f&7;
    cpa16(sbu + (uint32_t)(0*KA_ASZ + row*KA_ALD + q*4)*4, m4 + row*64 + 0*8 + q);
  }
  CP_COMMIT(); CP_WAIT0();
  __syncthreads();

  // mask sum (warp 0)
  if (t < 32){
    float s = sm[KA_MSK+t] + sm[KA_MSK+t+32] + sm[KA_MSK+t+64] + sm[KA_MSK+t+96];
    #pragma unroll
    for (int o=16;o;o>>=1) s += __shfl_xor_sync(0xffffffffu, s, o);
    if (t==0) g_msum_part[r*NTA + tile] = s;
  }

  const int ar0 = wm*32 + lq;
  const int bn0 = wn*32 + lq;
  float acc[2][4][4];
  #pragma unroll
  for (int mi=0;mi<2;mi++)
    #pragma unroll
    for (int ni=0;ni<4;ni++)
      #pragma unroll
      for (int q=0;q<4;q++) acc[mi][ni][q]=0.f;

  const int qch = t>>3, qsub = t&7;   // qpool: 8 threads per channel

  for (int kc=0;kc<8;kc++){
    if (kc<7){
      #pragma unroll
      for (int i=0;i<4;i++){
        int f = i*256 + t; int row = f>>3, q = f&7;
        cpa16(sbu + (uint32_t)(((kc+1)&1)*KA_ASZ + row*KA_ALD + q*4)*4,
              m4 + row*64 + (kc+1)*8 + q);
      }
      CP_COMMIT();
    }
    const float* As = sm + (kc&1)*KA_ASZ;
    const float* Bs = sm + KA_BOFF;
    #pragma unroll
    for (int s=0;s<4;s++){
      const int k0  = s*8 + lr;            // A chunk-relative k
      const int kb0 = kc*32 + k0;          // B absolute k
      uint32_t a[2][4], b[4][2];
      #pragma unroll
      for (int mi=0;mi<2;mi++){
        const float* ap = As + (ar0 + mi*16)*KA_ALD + k0;
        a[mi][0]=__float_as_uint(ap[0]);
        a[mi][1]=__float_as_uint(ap[8*KA_ALD]);
        a[mi][2]=__float_as_uint(ap[4]);
        a[mi][3]=__float_as_uint(ap[8*KA_ALD+4]);
      }
      #pragma unroll
      for (int ni=0;ni<4;ni++){
        const float* bp = Bs + (bn0 + ni*8)*KA_BLD + kb0;
        b[ni][0]=__float_as_uint(bp[0]);
        b[ni][1]=__float_as_uint(bp[4]);
      }
      #pragma unroll
      for (int mi=0;mi<2;mi++)
        #pragma unroll
        for (int ni=0;ni<4;ni++)
          mma8(acc[mi][ni], a[mi], b[ni]);
    }
    // fused qpool partial for channels kc*32 .. kc*32+31 (exact fp32)
    {
      float qa = 0.f;
      #pragma unroll
      for (int j=0;j<16;j++){
        int row = qsub + 8*j;
        qa += As[row*KA_ALD + qch] * sm[KA_MSK + row];
      }
      qa += __shfl_xor_sync(0xffffffffu, qa, 4);
      qa += __shfl_xor_sync(0xffffffffu, qa, 2);
      qa += __shfl_xor_sync(0xffffffffu, qa, 1);
      if (qsub==0) g_qpool_part[(r*NTA + tile)*CDIM + kc*32 + qch] = qa;
    }
    if (kc<7) CP_WAIT0();
    __syncthreads();
  }

  // store k/v
  #pragma unroll
  for (int mi=0;mi<2;mi++){
    #pragma unroll
    for (int ni=0;ni<4;ni++){
      const int col0 = wn*32 + ni*8 + lr*2;
      const int row0 = wm*32 + mi*16 + lq;
      *(float2*)(g_kv + (size_t)(r*SDIM + s0 + row0)*64 + col0) =
          make_float2(acc[mi][ni][0], acc[mi][ni][1]);
      *(float2*)(g_kv + (size_t)(r*SDIM + s0 + row0+8)*64 + col0) =
          make_float2(acc[mi][ni][2], acc[mi][ni][3]);
    }
  }
}

// ---------------- Kernel B: q, logits, softmax, o (fp32) ----------------
__global__ void __launch_bounds__(256) kb_attn(const float* __restrict__ mask,
                                               const float* __restrict__ Wq)
{
  __shared__ float qp[256];
  __shared__ float qh[256];
  __shared__ float lg[8*1024];
  __shared__ float vs[64*36];
  __shared__ float msum_s;
  const int t = threadIdx.x, r = blockIdx.x;

  float qa = 0.f;
  #pragma unroll
  for (int i=0;i<NTA;i++) qa += g_qpool_part[(r*NTA+i)*CDIM + t];
  if (t==0){
    float s=0.f;
    #pragma unroll
    for (int i=0;i<NTA;i++) s += g_msum_part[r*NTA+i];
    msum_s = s;
  }
  __syncthreads();
  qp[t] = qa / (msum_s + 1e-10f);
  __syncthreads();

  float qv = 0.f;
  for (int c=0;c<CDIM;c++) qv += qp[c]*Wq[c*256+t];
  qh[t] = qv * 0.17677669529663687f;
  __syncthreads();

  for (int it=0; it<4; it++){
    int s = it*256 + t;
    float kreg[32];
    const float* kv = g_kv + (size_t)(r*SDIM+s)*64;
    #pragma unroll
    for (int q=0;q<8;q++){
      float4 v4 = *(const float4*)(kv+4*q);
      kreg[4*q]=v4.x; kreg[4*q+1]=v4.y; kreg[4*q+2]=v4.z; kreg[4*q+3]=v4.w;
    }
    float bias = 1.0e9f*(mask[r*SDIM+s]-1.0f);
    #pragma unroll
    for (int h=0;h<8;h++){
      float d=0.f;
      #pragma unroll
      for (int q=0;q<32;q++) d += qh[h*32+q]*kreg[q];
      lg[h*1024+s] = d + bias;
    }
  }
  __syncthreads();

  const int w = t>>5, lane = t&31;
  {
    float mx = -3.4e38f;
    for (int s=lane; s<1024; s+=32) mx = fmaxf(mx, lg[w*1024+s]);
    #pragma unroll
    for (int o=16;o;o>>=1) mx = fmaxf(mx, __shfl_xor_sync(0xffffffffu, mx, o));
    float sum = 0.f;
    for (int s=lane; s<1024; s+=32){
      float e = __expf(lg[w*1024+s]-mx);
      lg[w*1024+s] = e; sum += e;
    }
    #pragma unroll
    for (int o=16;o;o>>=1) sum += __shfl_xor_sync(0xffffffffu, sum, o);
    float inv = 1.0f/sum;
    for (int s=lane; s<1024; s+=32) lg[w*1024+s] *= inv;
  }
  __syncthreads();

  float acc = 0.f;
  for (int tile=0;tile<16;tile++){
    #pragma unroll
    for (int i=0;i<2;i++){
      int f=t*2+i; int tk=f>>3, q=f&7;
      float4 v4 = *(const float4*)(g_kv + (size_t)(r*SDIM+tile*64+tk)*64 + 32 + 4*q);
      *(float4*)(vs + tk*36 + 4*q) = v4;
    }
    __syncthreads();
    #pragma unroll 8
    for (int tk=0;tk<64;tk++) acc += lg[w*1024 + tile*64+tk] * vs[tk*36 + lane];
    __syncthreads();
  }
  g_gate[r*CDIM + t] = acc;
}

// ---------------- Kernel C: out = (sigmoid(m@Wg+bg)*o) @ Wo + bo  (tf32 mma.sync) ----------------
// 256 threads = 8 warps (2x4), warp tile 64x64. CTA tile 128x256, K chunks of 32.
#define KCM     128
#define AC_LD   36
#define AC_SZ   (128*36)
#define TS_LD   260
#define TS_SZ   (128*260)
#define BS_OFF  TS_SZ
#define BS_SZ   (256*36)
#define OG_OFF  (BS_OFF + 2*BS_SZ)
#define BG_OFF  (OG_OFF + 256)
#define BO_OFF  (BG_OFF + 256)
#define KC_SMEM_BYTES ((BO_OFF + 256)*4)   // 209920

__device__ __forceinline__ void chunk_mma4(const float* __restrict__ As, int ldA,
                                           const float* __restrict__ Bs,
                                           int ar0, int bn0, int lr,
                                           float acc[4][8][4])
{
  #pragma unroll
  for (int s=0;s<4;s++){
    const int k0 = s*8 + lr;
    uint32_t a[4][4], b[8][2];
    #pragma unroll
    for (int mi=0;mi<4;mi++){
      const float* ap = As + (ar0 + mi*16)*ldA + k0;
      a[mi][0]=__float_as_uint(ap[0]);
      a[mi][1]=__float_as_uint(ap[8*ldA]);
      a[mi][2]=__float_as_uint(ap[4]);
      a[mi][3]=__float_as_uint(ap[8*ldA+4]);
    }
    #pragma unroll
    for (int ni=0;ni<8;ni++){
      const float* bp = Bs + (bn0 + ni*8)*AC_LD + k0;
      b[ni][0]=__float_as_uint(bp[0]);
      b[ni][1]=__float_as_uint(bp[4]);
    }
    #pragma unroll
    for (int mi=0;mi<4;mi++)
      #pragma unroll
      for (int ni=0;ni<8;ni++)
        mma8(acc[mi][ni], a[mi], b[ni]);
  }
}

__global__ void __launch_bounds__(256,1) kc_mma(const float* __restrict__ m,
    const float* __restrict__ bgp, const float* __restrict__ bop,
    float* __restrict__ out)
{
  extern __shared__ float sm[];
  const uint32_t sbu = s2u(sm);
  const int t = threadIdx.x, lane = t&31, w = t>>5;
  const int wm = w>>2, wn = w&3;            // 2 x 4 warp grid
  const int lq = lane>>2, lr = lane&3;
  const int r = blockIdx.y, tile = blockIdx.x, s0 = tile*KCM;

  sm[OG_OFF+t] = g_gate[r*CDIM+t];
  sm[BG_OFF+t] = bgp[t];
  sm[BO_OFF+t] = bop[t];

  const float4* m4   = (const float4*)(m + (size_t)(r*SDIM + s0)*CDIM);
  const float4* WgT4 = (const float4*)g_WgT;
  const float4* WoT4 = (const float4*)g_WoT;

  const int ar0 = wm*64 + lq;               // 4 mi tiles of 16 rows
  const int bn0 = wn*64 + lq;               // 8 ni tiles of 8 cols

  float acc[4][8][4];
  #pragma unroll
  for (int mi=0;mi<4;mi++)
    #pragma unroll
    for (int ni=0;ni<8;ni++)
      #pragma unroll
      for (int q=0;q<4;q++) acc[mi][ni][q]=0.f;

  // A chunk: 1024 f4 (4/thread); B chunk: 2048 f4 (8/thread)
  #define LOAD_A(kc, b) do { \
    _Pragma("unroll") \
    for (int i=0;i<4;i++){ \
      int f=i*256+t; int row=f>>3, q=f&7; \
      cpa16(sbu + (uint32_t)((b)*AC_SZ + row*AC_LD + q*4)*4, m4 + row*64 + (kc)*8 + q); \
    } } while(0)
  #define LOAD_B(W4, kc, b) do { \
    _Pragma("unroll") \
    for (int i=0;i<8;i++){ \
      int f=i*256+t; int n=f>>3, q=f&7; \
      cpa16(sbu + (uint32_t)(BS_OFF + (b)*BS_SZ + n*AC_LD + q*4)*4, (W4) + n*64 + (kc)*8 + q); \
    } } while(0)

  // ================= GEMM1: G = X @ WgT =================
  LOAD_A(0,0); LOAD_B(WgT4,0,0); CP_COMMIT();
  CP_WAIT0(); __syncthreads();
  for (int kc=0;kc<8;kc++){
    if (kc<7){ LOAD_A(kc+1,(kc+1)&1); LOAD_B(WgT4,kc+1,(kc+1)&1); CP_COMMIT(); }
    chunk_mma4(sm + (kc&1)*AC_SZ, AC_LD, sm + BS_OFF + (kc&1)*BS_SZ, ar0, bn0, lr, acc);
    if (kc<7) CP_WAIT0();
    __syncthreads();
  }

  LOAD_B(WoT4,0,0); CP_COMMIT();

  // ---- Epilogue 1: T = og * sigmoid(G + bg), tf32-RNA, into Ts ----
  #pragma unroll
  for (int mi=0;mi<4;mi++){
    #pragma unroll
    for (int ni=0;ni<8;ni++){
      const int col0 = wn*64 + ni*8 + lr*2;
      const int row0 = wm*64 + mi*16 + lq;
      const float bg0 = sm[BG_OFF+col0], bg1 = sm[BG_OFF+col0+1];
      const float o0  = sm[OG_OFF+col0], o1  = sm[OG_OFF+col0+1];
      float t00 = __fdividef(o0, 1.f+__expf(-(acc[mi][ni][0]+bg0)));
      float t01 = __fdividef(o1, 1.f+__expf(-(acc[mi][ni][1]+bg1)));
      float t10 = __fdividef(o0, 1.f+__expf(-(acc[mi][ni][2]+bg0)));
      float t11 = __fdividef(o1, 1.f+__expf(-(acc[mi][ni][3]+bg1)));
      *(float2*)(sm + row0*TS_LD + col0) =
          make_float2(__uint_as_float(tf32r(t00)), __uint_as_float(tf32r(t01)));
      *(float2*)(sm + (row0+8)*TS_LD + col0) =
          make_float2(__uint_as_float(tf32r(t10)), __uint_as_float(tf32r(t11)));
      #pragma unroll
      for (int q=0;q<4;q++) acc[mi][ni][q]=0.f;
    }
  }
  CP_WAIT0();
  __syncthreads();

  // ================= GEMM2: out = T @ WoT =================
  for (int kc=0;kc<8;kc++){
    if (kc<7){ LOAD_B(WoT4,kc+1,(kc+1)&1); CP_COMMIT(); }
    chunk_mma4(sm + kc*32, TS_LD, sm + BS_OFF + (kc&1)*BS_SZ, ar0, bn0, lr, acc);
    if (kc<7) CP_WAIT0();
    __syncthreads();
  }

  // ---- Epilogue 2: add bo, store ----
  #pragma unroll
  for (int mi=0;mi<4;mi++){
    #pragma unroll
    for (int ni=0;ni<8;ni++){
      const int col0 = wn*64 + ni*8 + lr*2;
      const int row0 = wm*64 + mi*16 + lq;
      const float b0 = sm[BO_OFF+col0], b1 = sm[BO_OFF+col0+1];
      *(float2*)(out + (size_t)(r*SDIM + s0 + row0)*CDIM + col0) =
          make_float2(acc[mi][ni][0]+b0, acc[mi][ni][1]+b1);
      *(float2*)(out + (size_t)(r*SDIM + s0 + row0+8)*CDIM + col0) =
          make_float2(acc[mi][ni][2]+b0, acc[mi][ni][3]+b1);
    }
  }
  #undef LOAD_A
  #undef LOAD_B
}

// ---------------- launch ----------------
extern "C" void kernel_launch(void* const* d_in, const int* in_sizes, int n_in,
                              void* d_out, int out_size)
{
  const float* m    = (const float*)d_in[0];
  const float* mask = (const float*)d_in[1];
  const float* Wq   = (const float*)d_in[2];
  const float* Wk   = (const float*)d_in[3];
  const float* Wv   = (const float*)d_in[4];
  const float* Wg   = (const float*)d_in[5];
  const float* bg   = (const float*)d_in[6];
  const float* Wo   = (const float*)d_in[7];
  const float* bo   = (const float*)d_in[8];
  float* out = (float*)d_out;

  cudaFuncSetAttribute(ka_kv,  cudaFuncAttributeMaxDynamicSharedMemorySize, KA_SMEM);
  cudaFuncSetAttribute(kc_mma, cudaFuncAttributeMaxDynamicSharedMemorySize, KC_SMEM_BYTES);

  kprep <<<256, 256>>>(Wg, Wo, Wk, Wv);
  ka_kv <<<dim3(NTA, RDIM), 256, KA_SMEM>>>(m, mask);
  kb_attn<<<RDIM, 256>>>(mask, Wq);
  kc_mma<<<dim3(8, RDIM), 256, KC_SMEM_BYTES>>>(m, bg, bo, out);
}

// round 7
// speedup vs baseline: 4.0449x; 1.0535x over previous
#include <cuda_runtime.h>
#include <math.h>
#include <stdint.h>

#define RDIM 256
#define SDIM 1024
#define CDIM 256
#define NTA  8          // 128-token tiles per row

typedef unsigned long long ull;

// ---------------- device scratch ----------------
__device__ float g_kv[RDIM*SDIM*64];          // per token: [0:32)=k, [32:64)=v
__device__ float g_qpool_part[RDIM*NTA*CDIM];
__device__ float g_msum_part[RDIM*NTA];
__device__ float g_gate[RDIM*CDIM];           // attention output o[r, h*32+c]
__device__ float g_WgT[CDIM*CDIM];            // Wg transposed [n][k], tf32 RNA
__device__ float g_WoT[CDIM*CDIM];            // Wo transposed [n][k], tf32 RNA
__device__ float g_WkvT[64*CDIM];             // [Wk|Wv] transposed [n][k], tf32 RNA

// ---------------- helpers ----------------
__device__ __forceinline__ uint32_t s2u(const void* p){
  uint32_t a;
  asm("{ .reg .u64 t; cvta.to.shared.u64 t, %1; cvt.u32.u64 %0, t; }" : "=r"(a) : "l"(p));
  return a;
}
__device__ __forceinline__ uint32_t tf32r(float x){
  uint32_t u; asm("cvt.rna.tf32.f32 %0, %1;" : "=r"(u) : "f"(x)); return u;
}
__device__ __forceinline__ void cpa16(uint32_t dst, const void* src){
  asm volatile("cp.async.cg.shared.global [%0], [%1], 16;" :: "r"(dst), "l"(src));
}
#define CP_COMMIT() asm volatile("cp.async.commit_group;" ::: "memory")
#define CP_WAIT0()  asm volatile("cp.async.wait_group 0;" ::: "memory")

__device__ __forceinline__ void mma8(float d[4], const uint32_t a[4], const uint32_t b[2]){
  asm volatile(
    "mma.sync.aligned.m16n8k8.row.col.f32.tf32.tf32.f32 "
    "{%0,%1,%2,%3}, {%4,%5,%6,%7}, {%8,%9}, {%0,%1,%2,%3};"
    : "+f"(d[0]), "+f"(d[1]), "+f"(d[2]), "+f"(d[3])
    : "r"(a[0]), "r"(a[1]), "r"(a[2]), "r"(a[3]), "r"(b[0]), "r"(b[1]));
}
__device__ __forceinline__ void ldsm4(uint32_t &r0, uint32_t &r1, uint32_t &r2, uint32_t &r3,
                                      uint32_t addr){
  asm volatile("ldmatrix.sync.aligned.m8n8.x4.shared.b16 {%0,%1,%2,%3}, [%4];"
    : "=r"(r0), "=r"(r1), "=r"(r2), "=r"(r3) : "r"(addr));
}

// ---------------- Kernel P: transpose + tf32-round weights ----------------
__global__ void __launch_bounds__(256) kprep(const float* __restrict__ Wg,
                                             const float* __restrict__ Wo,
                                             const float* __restrict__ Wk,
                                             const float* __restrict__ Wv)
{
  const int n = blockIdx.x, k = threadIdx.x;
  g_WgT[n*CDIM + k] = __uint_as_float(tf32r(Wg[k*CDIM + n]));
  g_WoT[n*CDIM + k] = __uint_as_float(tf32r(Wo[k*CDIM + n]));
  if (n < 32)       g_WkvT[n*CDIM + k]      = __uint_as_float(tf32r(Wk[k*32 + n]));
  else if (n < 64)  g_WkvT[n*CDIM + k]      = __uint_as_float(tf32r(Wv[k*32 + (n-32)]));
}

// ---------------- Kernel A: k/v projection (tf32 mma) + fused qpool ----------------
// grid (NTA, RDIM), 256 threads (8 warps, 4x2), CTA tile 128 tok x 64 out, K=256.
#define KA_ALD   36
#define KA_ASZ   (128*KA_ALD)          // 4608 floats per A buffer
#define KA_BOFF  (2*KA_ASZ)            // 9216
#define KA_BLD   260
#define KA_MSK   (KA_BOFF + 64*KA_BLD) // 25856
#define KA_SMEM  ((KA_MSK + 128)*4)    // 103936 B

__global__ void __launch_bounds__(256,2) ka_kv(const float* __restrict__ m,
                                               const float* __restrict__ mask)
{
  extern __shared__ float sm[];
  const uint32_t sbu = s2u(sm);
  const int t = threadIdx.x, lane = t&31, w = t>>5;
  const int wm = w>>1, wn = w&1;
  const int lq = lane>>2, lr = lane&3;
  const int r = blockIdx.y, tile = blockIdx.x, s0 = tile*128;

  const float4* m4 = (const float4*)(m + (size_t)(r*SDIM + s0)*CDIM);
  const float4* B4 = (const float4*)g_WkvT;

  // stage mask
  if (t < 128) sm[KA_MSK + t] = mask[r*SDIM + s0 + t];

  // stage full B (64 x 256 = 4096 f4)
  #pragma unroll
  for (int i=0;i<16;i++){
    int f = i*256 + t; int n = f>>6, q = f&63;
    cpa16(sbu + (uint32_t)(KA_BOFF + n*KA_BLD + q*4)*4, B4 + n*64 + q);
  }
  // A chunk 0
  #pragma unroll
  for (int i=0;i<4;i++){
    int f = i*256 + t; int row = f>>3, q = f&7;
    cpa16(sbu + (uint32_t)(0*KA_ASZ + row*KA_ALD + q*4)*4, m4 + row*64 + 0*8 + q);
  }
  CP_COMMIT(); CP_WAIT0();
  __syncthreads();

  // mask sum (warp 0)
  if (t < 32){
    float s = sm[KA_MSK+t] + sm[KA_MSK+t+32] + sm[KA_MSK+t+64] + sm[KA_MSK+t+96];
    #pragma unroll
    for (int o=16;o;o>>=1) s += __shfl_xor_sync(0xffffffffu, s, o);
    if (t==0) g_msum_part[r*NTA + tile] = s;
  }

  const int ar0 = wm*32 + lq;
  const int bn0 = wn*32 + lq;
  float acc[2][4][4];
  #pragma unroll
  for (int mi=0;mi<2;mi++)
    #pragma unroll
    for (int ni=0;ni<4;ni++)
      #pragma unroll
      for (int q=0;q<4;q++) acc[mi][ni][q]=0.f;

  const int qch = t>>3, qsub = t&7;   // qpool: 8 threads per channel

  for (int kc=0;kc<8;kc++){
    if (kc<7){
      #pragma unroll
      for (int i=0;i<4;i++){
        int f = i*256 + t; int row = f>>3, q = f&7;
        cpa16(sbu + (uint32_t)(((kc+1)&1)*KA_ASZ + row*KA_ALD + q*4)*4,
              m4 + row*64 + (kc+1)*8 + q);
      }
      CP_COMMIT();
    }
    const float* As = sm + (kc&1)*KA_ASZ;
    const float* Bs = sm + KA_BOFF;
    #pragma unroll
    for (int s=0;s<4;s++){
      const int k0  = s*8 + lr;            // A chunk-relative k
      const int kb0 = kc*32 + k0;          // B absolute k
      uint32_t a[2][4], b[4][2];
      #pragma unroll
      for (int mi=0;mi<2;mi++){
        const float* ap = As + (ar0 + mi*16)*KA_ALD + k0;
        a[mi][0]=__float_as_uint(ap[0]);
        a[mi][1]=__float_as_uint(ap[8*KA_ALD]);
        a[mi][2]=__float_as_uint(ap[4]);
        a[mi][3]=__float_as_uint(ap[8*KA_ALD+4]);
      }
      #pragma unroll
      for (int ni=0;ni<4;ni++){
        const float* bp = Bs + (bn0 + ni*8)*KA_BLD + kb0;
        b[ni][0]=__float_as_uint(bp[0]);
        b[ni][1]=__float_as_uint(bp[4]);
      }
      #pragma unroll
      for (int mi=0;mi<2;mi++)
        #pragma unroll
        for (int ni=0;ni<4;ni++)
          mma8(acc[mi][ni], a[mi], b[ni]);
    }
    // fused qpool partial for channels kc*32 .. kc*32+31 (exact fp32)
    {
      float qa = 0.f;
      #pragma unroll
      for (int j=0;j<16;j++){
        int row = qsub + 8*j;
        qa += As[row*KA_ALD + qch] * sm[KA_MSK + row];
      }
      qa += __shfl_xor_sync(0xffffffffu, qa, 4);
      qa += __shfl_xor_sync(0xffffffffu, qa, 2);
      qa += __shfl_xor_sync(0xffffffffu, qa, 1);
      if (qsub==0) g_qpool_part[(r*NTA + tile)*CDIM + kc*32 + qch] = qa;
    }
    if (kc<7) CP_WAIT0();
    __syncthreads();
  }

  // store k/v
  #pragma unroll
  for (int mi=0;mi<2;mi++){
    #pragma unroll
    for (int ni=0;ni<4;ni++){
      const int col0 = wn*32 + ni*8 + lr*2;
      const int row0 = wm*32 + mi*16 + lq;
      *(float2*)(g_kv + (size_t)(r*SDIM + s0 + row0)*64 + col0) =
          make_float2(acc[mi][ni][0], acc[mi][ni][1]);
      *(float2*)(g_kv + (size_t)(r*SDIM + s0 + row0+8)*64 + col0) =
          make_float2(acc[mi][ni][2], acc[mi][ni][3]);
    }
  }
}

// ---------------- Kernel B: q, logits, softmax, o (fp32) ----------------
__global__ void __launch_bounds__(256) kb_attn(const float* __restrict__ mask,
                                               const float* __restrict__ Wq)
{
  __shared__ float qp[256];
  __shared__ float qh[256];
  __shared__ float lg[8*1024];
  __shared__ float vs[64*36];
  __shared__ float msum_s;
  const int t = threadIdx.x, r = blockIdx.x;

  float qa = 0.f;
  #pragma unroll
  for (int i=0;i<NTA;i++) qa += g_qpool_part[(r*NTA+i)*CDIM + t];
  if (t==0){
    float s=0.f;
    #pragma unroll
    for (int i=0;i<NTA;i++) s += g_msum_part[r*NTA+i];
    msum_s = s;
  }
  __syncthreads();
  qp[t] = qa / (msum_s + 1e-10f);
  __syncthreads();

  float qv = 0.f;
  for (int c=0;c<CDIM;c++) qv += qp[c]*Wq[c*256+t];
  qh[t] = qv * 0.17677669529663687f;
  __syncthreads();

  for (int it=0; it<4; it++){
    int s = it*256 + t;
    float kreg[32];
    const float* kv = g_kv + (size_t)(r*SDIM+s)*64;
    #pragma unroll
    for (int q=0;q<8;q++){
      float4 v4 = *(const float4*)(kv+4*q);
      kreg[4*q]=v4.x; kreg[4*q+1]=v4.y; kreg[4*q+2]=v4.z; kreg[4*q+3]=v4.w;
    }
    float bias = 1.0e9f*(mask[r*SDIM+s]-1.0f);
    #pragma unroll
    for (int h=0;h<8;h++){
      float d=0.f;
      #pragma unroll
      for (int q=0;q<32;q++) d += qh[h*32+q]*kreg[q];
      lg[h*1024+s] = d + bias;
    }
  }
  __syncthreads();

  const int w = t>>5, lane = t&31;
  {
    float mx = -3.4e38f;
    for (int s=lane; s<1024; s+=32) mx = fmaxf(mx, lg[w*1024+s]);
    #pragma unroll
    for (int o=16;o;o>>=1) mx = fmaxf(mx, __shfl_xor_sync(0xffffffffu, mx, o));
    float sum = 0.f;
    for (int s=lane; s<1024; s+=32){
      float e = __expf(lg[w*1024+s]-mx);
      lg[w*1024+s] = e; sum += e;
    }
    #pragma unroll
    for (int o=16;o;o>>=1) sum += __shfl_xor_sync(0xffffffffu, sum, o);
    float inv = 1.0f/sum;
    for (int s=lane; s<1024; s+=32) lg[w*1024+s] *= inv;
  }
  __syncthreads();

  float acc = 0.f;
  for (int tile=0;tile<16;tile++){
    #pragma unroll
    for (int i=0;i<2;i++){
      int f=t*2+i; int tk=f>>3, q=f&7;
      float4 v4 = *(const float4*)(g_kv + (size_t)(r*SDIM+tile*64+tk)*64 + 32 + 4*q);
      *(float4*)(vs + tk*36 + 4*q) = v4;
    }
    __syncthreads();
    #pragma unroll 8
    for (int tk=0;tk<64;tk++) acc += lg[w*1024 + tile*64+tk] * vs[tk*36 + lane];
    __syncthreads();
  }
  g_gate[r*CDIM + t] = acc;
}

// ---------------- Kernel C: out = (sigmoid(m@Wg+bg)*o) @ Wo + bo  (tf32 mma + ldmatrix) ----------------
// 512 threads = 16 warps (4x4), warp tile 32x64. CTA tile 128x256, K chunks of 32.
#define KCM     128
#define AC_LD   36
#define AC_SZ   (128*36)
#define TS_LD   260
#define TS_SZ   (128*260)
#define BS_OFF  TS_SZ
#define BS_SZ   (256*36)
#define OG_OFF  (BS_OFF + 2*BS_SZ)
#define BG_OFF  (OG_OFF + 256)
#define BO_OFF  (BG_OFF + 256)
#define KC_SMEM_BYTES ((BO_OFF + 256)*4)   // 209920

__global__ void __launch_bounds__(512,1) kc_mma(const float* __restrict__ m,
    const float* __restrict__ bgp, const float* __restrict__ bop,
    float* __restrict__ out)
{
  extern __shared__ float sm[];
  const uint32_t sbu = s2u(sm);
  const int t = threadIdx.x, lane = t&31, w = t>>5;
  const int wm = w>>2, wn = w&3;
  const int lq = lane>>2, lr = lane&3;
  const int til = lane>>3, rw = lane&7;    // ldmatrix tile/row within x4
  const int r = blockIdx.y, tile = blockIdx.x, s0 = tile*KCM;

  if (t < 256){
    sm[OG_OFF+t] = g_gate[r*CDIM+t];
    sm[BG_OFF+t] = bgp[t];
    sm[BO_OFF+t] = bop[t];
  }

  const float4* m4   = (const float4*)(m + (size_t)(r*SDIM + s0)*CDIM);
  const float4* WgT4 = (const float4*)g_WgT;
  const float4* WoT4 = (const float4*)g_WoT;

  // ldmatrix per-lane byte offsets:
  // A pattern (rows 16, k 8): tile0 rows0-7@k0, tile1 rows8-15@k0, tile2 rows0-7@k+4, tile3 rows8-15@k+4
  const uint32_t offA36  = (uint32_t)((((til&1)*8 + rw)*AC_LD)*4 + (til>>1)*16);
  const uint32_t offA260 = (uint32_t)((((til&1)*8 + rw)*TS_LD)*4 + (til>>1)*16);
  // B pattern (ni pair: 16 n-rows, k 8): tile0 n0-7@k0, tile1 n0-7@k+4, tile2 n8-15@k0, tile3 n8-15@k+4
  const uint32_t offB36  = (uint32_t)((((til>>1)*8 + rw)*AC_LD)*4 + (til&1)*16);

  float acc[2][8][4];
  #pragma unroll
  for (int mi=0;mi<2;mi++)
    #pragma unroll
    for (int ni=0;ni<8;ni++)
      #pragma unroll
      for (int q=0;q<4;q++) acc[mi][ni][q]=0.f;

  #define LOAD_A(kc, b) do { \
    _Pragma("unroll") \
    for (int i=0;i<2;i++){ \
      int f=i*512+t; int row=f>>3, q=f&7; \
      cpa16(sbu + (uint32_t)((b)*AC_SZ + row*AC_LD + q*4)*4, m4 + row*64 + (kc)*8 + q); \
    } } while(0)
  #define LOAD_B(W4, kc, b) do { \
    _Pragma("unroll") \
    for (int i=0;i<4;i++){ \
      int f=i*512+t; int n=f>>3, q=f&7; \
      cpa16(sbu + (uint32_t)(BS_OFF + (b)*BS_SZ + n*AC_LD + q*4)*4, (W4) + n*64 + (kc)*8 + q); \
    } } while(0)

  #define CHUNK_MMA(aBase, bBase) do { \
    _Pragma("unroll") \
    for (int s=0;s<4;s++){ \
      uint32_t a[2][4], b[8][2]; \
      ldsm4(a[0][0],a[0][1],a[0][2],a[0][3], (aBase) + s*32); \
      ldsm4(a[1][0],a[1][1],a[1][2],a[1][3], (aBase) + (uint32_t)(16*ALD_CUR*4) + s*32); \
      ldsm4(b[0][0],b[0][1],b[1][0],b[1][1], (bBase) + s*32); \
      ldsm4(b[2][0],b[2][1],b[3][0],b[3][1], (bBase) + (uint32_t)(16*AC_LD*4) + s*32); \
      ldsm4(b[4][0],b[4][1],b[5][0],b[5][1], (bBase) + (uint32_t)(32*AC_LD*4) + s*32); \
      ldsm4(b[6][0],b[6][1],b[7][0],b[7][1], (bBase) + (uint32_t)(48*AC_LD*4) + s*32); \
      _Pragma("unroll") \
      for (int mi=0;mi<2;mi++) \
        _Pragma("unroll") \
        for (int ni=0;ni<8;ni++) \
          mma8(acc[mi][ni], a[mi], b[ni]); \
    } } while(0)

  // ================= GEMM1: G = X @ WgT =================
  LOAD_A(0,0); LOAD_B(WgT4,0,0); CP_COMMIT();
  CP_WAIT0(); __syncthreads();
  for (int kc=0;kc<8;kc++){
    if (kc<7){ LOAD_A(kc+1,(kc+1)&1); LOAD_B(WgT4,kc+1,(kc+1)&1); CP_COMMIT(); }
    {
      #define ALD_CUR AC_LD
      uint32_t aB = sbu + (uint32_t)(((kc&1)*AC_SZ + wm*32*AC_LD)*4) + offA36;
      uint32_t bB = sbu + (uint32_t)((BS_OFF + (kc&1)*BS_SZ + wn*64*AC_LD)*4) + offB36;
      CHUNK_MMA(aB, bB);
      #undef ALD_CUR
    }
    if (kc<7) CP_WAIT0();
    __syncthreads();
  }

  LOAD_B(WoT4,0,0); CP_COMMIT();

  // ---- Epilogue 1: T = og * sigmoid(G + bg), tf32-RNA, into Ts ----
  #pragma unroll
  for (int mi=0;mi<2;mi++){
    #pragma unroll
    for (int ni=0;ni<8;ni++){
      const int col0 = wn*64 + ni*8 + lr*2;
      const int row0 = wm*32 + mi*16 + lq;
      const float bg0 = sm[BG_OFF+col0], bg1 = sm[BG_OFF+col0+1];
      const float o0  = sm[OG_OFF+col0], o1  = sm[OG_OFF+col0+1];
      float t00 = __fdividef(o0, 1.f+__expf(-(acc[mi][ni][0]+bg0)));
      float t01 = __fdividef(o1, 1.f+__expf(-(acc[mi][ni][1]+bg1)));
      float t10 = __fdividef(o0, 1.f+__expf(-(acc[mi][ni][2]+bg0)));
      float t11 = __fdividef(o1, 1.f+__expf(-(acc[mi][ni][3]+bg1)));
      *(float2*)(sm + row0*TS_LD + col0) =
          make_float2(__uint_as_float(tf32r(t00)), __uint_as_float(tf32r(t01)));
      *(float2*)(sm + (row0+8)*TS_LD + col0) =
          make_float2(__uint_as_float(tf32r(t10)), __uint_as_float(tf32r(t11)));
      #pragma unroll
      for (int q=0;q<4;q++) acc[mi][ni][q]=0.f;
    }
  }
  CP_WAIT0();
  __syncthreads();

  // ================= GEMM2: out = T @ WoT =================
  for (int kc=0;kc<8;kc++){
    if (kc<7){ LOAD_B(WoT4,kc+1,(kc+1)&1); CP_COMMIT(); }
    {
      #define ALD_CUR TS_LD
      uint32_t aB = sbu + (uint32_t)((wm*32*TS_LD + kc*32)*4) + offA260;
      uint32_t bB = sbu + (uint32_t)((BS_OFF + (kc&1)*BS_SZ + wn*64*AC_LD)*4) + offB36;
      CHUNK_MMA(aB, bB);
      #undef ALD_CUR
    }
    if (kc<7) CP_WAIT0();
    __syncthreads();
  }

  // ---- Epilogue 2: add bo, store ----
  #pragma unroll
  for (int mi=0;mi<2;mi++){
    #pragma unroll
    for (int ni=0;ni<8;ni++){
      const int col0 = wn*64 + ni*8 + lr*2;
      const int row0 = wm*32 + mi*16 + lq;
      const float b0 = sm[BO_OFF+col0], b1 = sm[BO_OFF+col0+1];
      *(float2*)(out + (size_t)(r*SDIM + s0 + row0)*CDIM + col0) =
          make_float2(acc[mi][ni][0]+b0, acc[mi][ni][1]+b1);
      *(float2*)(out + (size_t)(r*SDIM + s0 + row0+8)*CDIM + col0) =
          make_float2(acc[mi][ni][2]+b0, acc[mi][ni][3]+b1);
    }
  }
  #undef LOAD_A
  #undef LOAD_B
  #undef CHUNK_MMA
}

// ---------------- launch ----------------
extern "C" void kernel_launch(void* const* d_in, const int* in_sizes, int n_in,
                              void* d_out, int out_size)
{
  const float* m    = (const float*)d_in[0];
  const float* mask = (const float*)d_in[1];
  const float* Wq   = (const float*)d_in[2];
  const float* Wk   = (const float*)d_in[3];
  const float* Wv   = (const float*)d_in[4];
  const float* Wg   = (const float*)d_in[5];
  const float* bg   = (const float*)d_in[6];
  const float* Wo   = (const float*)d_in[7];
  const float* bo   = (const float*)d_in[8];
  float* out = (float*)d_out;

  cudaFuncSetAttribute(ka_kv,  cudaFuncAttributeMaxDynamicSharedMemorySize, KA_SMEM);
  cudaFuncSetAttribute(kc_mma, cudaFuncAttributeMaxDynamicSharedMemorySize, KC_SMEM_BYTES);

  kprep <<<256, 256>>>(Wg, Wo, Wk, Wv);
  ka_kv <<<dim3(NTA, RDIM), 256, KA_SMEM>>>(m, mask);
  kb_attn<<<RDIM, 256>>>(mask, Wq);
  kc_mma<<<dim3(8, RDIM), 512, KC_SMEM_BYTES>>>(m, bg, bo, out);
}